// round 7
// baseline (speedup 1.0000x reference)
#include <cuda_runtime.h>
#include <cuda_fp16.h>
#include <math.h>

#define NN 100000
#define EE 3200000
#define FF 128
#define HH 16
#define CC 40
#define ALPHA 0.1f
#define BN_EPS 1e-5f
#define SB 512                 // scan block size

// ---------------- scratch (device globals; no allocation) ----------------
__device__ __align__(16) __half g_tmps[NN * HH];  // fp16 (x@W1)*dinv (src-side, conv1)
__device__ __align__(16) __half g_h2s[NN * HH];   // fp16 post-hops hidden * dinv (src-side)
__device__ __align__(16) float g_h[NN * HH];      // fp32 post-relu hidden
__device__ float g_dinv[NN];
__device__ float g_stats[2 * HH];
// CSR machinery
__device__ int g_cnt[NN];          // in-degree (no self loop)
__device__ int g_off[NN];          // CSR row start (block-LOCAL; add g_bpre[node/SB])
__device__ int g_cur[NN];          // fill cursor (block-local base)
__device__ int g_btot[256];        // scan block totals
__device__ int g_bpre[256];        // scan block prefixes
__device__ int g_flag;             // last-block counter for scan1
__device__ int g_csr[EE];          // src indices grouped by dst

// ---------------- helpers ----------------
__device__ __forceinline__ void acc_h16(float4& a, float4& b, uint4 r) {
    float2 f0 = __half22float2(*reinterpret_cast<__half2*>(&r.x));
    float2 f1 = __half22float2(*reinterpret_cast<__half2*>(&r.y));
    float2 f2 = __half22float2(*reinterpret_cast<__half2*>(&r.z));
    float2 f3 = __half22float2(*reinterpret_cast<__half2*>(&r.w));
    a.x += f0.x; a.y += f0.y; a.z += f1.x; a.w += f1.y;
    b.x += f2.x; b.y += f2.y; b.z += f3.x; b.w += f3.y;
}

// ---------------- setup kernels ----------------

__global__ void k_init(int n) {
    int i = blockIdx.x * blockDim.x + threadIdx.x;
    if (i < n) g_cnt[i] = 0;
    if (i < 2 * HH) g_stats[i] = 0.0f;
    if (i == 2 * HH) g_flag = 0;
}

// 4 edges per thread, int4 loads
__global__ void k_cnt(const int* __restrict__ dst, int ne) {
    int i = blockIdx.x * blockDim.x + threadIdx.x;
    int base = i * 4;
    if (base + 3 < ne) {
        int4 d = ((const int4*)dst)[i];
        atomicAdd(&g_cnt[d.x], 1);
        atomicAdd(&g_cnt[d.y], 1);
        atomicAdd(&g_cnt[d.z], 1);
        atomicAdd(&g_cnt[d.w], 1);
    } else {
        for (int e = base; e < ne; e++) atomicAdd(&g_cnt[dst[e]], 1);
    }
}

// block-local exclusive scan of g_cnt + dinv + cursor init.
// LAST finishing block also scans the block totals into g_bpre.
__global__ void k_scan1(int n) {
    __shared__ int wsum[SB / 32];
    __shared__ int isLast;
    int t = threadIdx.x, b = blockIdx.x;
    int i = b * SB + t;
    int v = (i < n) ? g_cnt[i] : 0;
    int x = v;
    #pragma unroll
    for (int off = 1; off < 32; off <<= 1) {
        int y = __shfl_up_sync(0xffffffffu, x, off);
        if ((t & 31) >= off) x += y;
    }
    if ((t & 31) == 31) wsum[t >> 5] = x;
    __syncthreads();
    if (t < SB / 32) {
        int w = wsum[t];
        #pragma unroll
        for (int off = 1; off < SB / 32; off <<= 1) {
            int y = __shfl_up_sync((1u << (SB / 32)) - 1u, w, off);
            if (t >= off) w += y;
        }
        wsum[t] = w;
    }
    __syncthreads();
    int prefix = (t >= 32) ? wsum[(t >> 5) - 1] : 0;
    if (i < n) {
        int loc = prefix + x - v;
        g_off[i] = loc;
        g_cur[i] = loc;
        g_dinv[i] = rsqrtf((float)(v + 1));   // +1 self loop
    }
    if (t == SB - 1) g_btot[b] = prefix + x;

    __threadfence();
    __syncthreads();
    if (t == 0) {
        int c = atomicAdd(&g_flag, 1);
        isLast = (c == gridDim.x - 1);
    }
    __syncthreads();
    if (!isLast) return;

    int nb = gridDim.x;                  // <= 256
    if (t < 256) {
        __shared__ int wsum2[8];
        int bv = (t < nb) ? g_btot[t] : 0;
        int bx = bv;
        #pragma unroll
        for (int off = 1; off < 32; off <<= 1) {
            int y = __shfl_up_sync(0xffffffffu, bx, off);
            if ((t & 31) >= off) bx += y;
        }
        if ((t & 31) == 31) wsum2[t >> 5] = bx;
        __syncthreads();
        if (t < 8) {
            int w = wsum2[t];
            #pragma unroll
            for (int off = 1; off < 8; off <<= 1) {
                int y = __shfl_up_sync(0xffu, w, off);
                if (t >= off) w += y;
            }
            wsum2[t] = w;
        }
        __syncthreads();
        int bpre = (t >= 32) ? wsum2[(t >> 5) - 1] : 0;
        if (t < nb) g_bpre[t] = bpre + bx - bv;
    }
}

// 4 edges per thread, int4 loads, 4 atomic cursors in flight
__global__ void k_fill(const int* __restrict__ src, const int* __restrict__ dst, int ne) {
    int i = blockIdx.x * blockDim.x + threadIdx.x;
    int base = i * 4;
    if (base + 3 < ne) {
        int4 d = ((const int4*)dst)[i];
        int4 s = ((const int4*)src)[i];
        int p0 = atomicAdd(&g_cur[d.x], 1) + g_bpre[d.x >> 9];
        int p1 = atomicAdd(&g_cur[d.y], 1) + g_bpre[d.y >> 9];
        int p2 = atomicAdd(&g_cur[d.z], 1) + g_bpre[d.z >> 9];
        int p3 = atomicAdd(&g_cur[d.w], 1) + g_bpre[d.w >> 9];
        g_csr[p0] = s.x;
        g_csr[p1] = s.y;
        g_csr[p2] = s.z;
        g_csr[p3] = s.w;
    } else {
        for (int e = base; e < ne; e++) {
            int d = dst[e];
            int p = atomicAdd(&g_cur[d], 1) + g_bpre[d >> 9];
            g_csr[p] = src[e];
        }
    }
}

// ---------------- compute kernels ----------------

// x[N,128] @ W1[128,16] * dinv -> g_tmps (fp16). 64-node smem tile, 4 threads/node.
#define TILE 64
__global__ void __launch_bounds__(256) k_mm1(const float* __restrict__ x,
                                             const float* __restrict__ W1, int n) {
    __shared__ float4 xs[TILE][33];
    __shared__ float w1s[FF * HH];
    int t = threadIdx.x;
    int base = blockIdx.x * TILE;

    #pragma unroll
    for (int i = t; i < FF * HH; i += 256) w1s[i] = W1[i];

    const float4* xg = (const float4*)x;
    #pragma unroll
    for (int i = t; i < TILE * 32; i += 256) {
        int r = i >> 5, c = i & 31;
        float4 v = make_float4(0.f, 0.f, 0.f, 0.f);
        if (base + r < n) v = xg[(size_t)(base + r) * 32 + c];
        xs[r][c] = v;
    }
    __syncthreads();

    int ni = t >> 2;
    int jg = t & 3;
    int node = base + ni;

    const float* xrow = (const float*)&xs[ni][0];
    float a0 = 0.f, a1 = 0.f, a2 = 0.f, a3 = 0.f;
    #pragma unroll 8
    for (int k = 0; k < FF; k++) {
        float xv = xrow[k];
        float4 w = *(const float4*)&w1s[k * HH + jg * 4];
        a0 += xv * w.x; a1 += xv * w.y; a2 += xv * w.z; a3 += xv * w.w;
    }

    if (node < n) {
        float di = g_dinv[node];
        __half2 p0 = __floats2half2_rn(a0 * di, a1 * di);
        __half2 p1 = __floats2half2_rn(a2 * di, a3 * di);
        uint2 pk;
        pk.x = *reinterpret_cast<unsigned*>(&p0);
        pk.y = *reinterpret_cast<unsigned*>(&p1);
        ((uint2*)&g_tmps[(size_t)node * HH])[jg] = pk;
    }
}

// gather body: 16 slots/warp, uint4 (16B = half row) per lane, unroll 2
__device__ __forceinline__ void gather_row_sum16(const uint4* __restrict__ inp,
                                                 int beg, int cnt, int slot, int c,
                                                 float4& A, float4& B) {
    int j = slot;
    for (; j + 16 < cnt; j += 32) {
        int s0 = g_csr[beg + j];
        int s1 = g_csr[beg + j + 16];
        uint4 r0 = inp[(size_t)s0 * 2 + c];
        uint4 r1 = inp[(size_t)s1 * 2 + c];
        acc_h16(A, B, r0);
        acc_h16(A, B, r1);
    }
    if (j < cnt) {
        int s = g_csr[beg + j];
        acc_h16(A, B, inp[(size_t)s * 2 + c]);
    }
}

// conv1 aggregation (fp16 gather, fp32 accum) + relu + bias -> g_h (fp32).
__global__ void __launch_bounds__(256) k_agg1(const float* __restrict__ b1, int n) {
    int t = threadIdx.x;
    int warp = (blockIdx.x * blockDim.x + t) >> 5;
    if (warp >= n) return;

    int lane = t & 31;
    int slot = lane >> 1;            // 0..15
    int c    = lane & 1;             // uint4 half of the 32B row
    int beg = g_off[warp] + g_bpre[warp >> 9];
    int cnt = g_cnt[warp];

    const uint4* inp = (const uint4*)g_tmps;
    float4 A = make_float4(0.f, 0.f, 0.f, 0.f);
    float4 B = make_float4(0.f, 0.f, 0.f, 0.f);
    if (slot == 0) acc_h16(A, B, inp[(size_t)warp * 2 + c]);   // self loop
    gather_row_sum16(inp, beg, cnt, slot, c, A, B);

    #pragma unroll
    for (int off = 2; off < 32; off <<= 1) {
        A.x += __shfl_xor_sync(0xffffffffu, A.x, off);
        A.y += __shfl_xor_sync(0xffffffffu, A.y, off);
        A.z += __shfl_xor_sync(0xffffffffu, A.z, off);
        A.w += __shfl_xor_sync(0xffffffffu, A.w, off);
        B.x += __shfl_xor_sync(0xffffffffu, B.x, off);
        B.y += __shfl_xor_sync(0xffffffffu, B.y, off);
        B.z += __shfl_xor_sync(0xffffffffu, B.z, off);
        B.w += __shfl_xor_sync(0xffffffffu, B.w, off);
    }
    if (lane < 2) {                  // lane == c : holds features [8c, 8c+8)
        float di = g_dinv[warp];
        int fb = 8 * lane;
        float4 ra = make_float4(
            fmaxf(di * A.x + __ldg(&b1[fb+0]), 0.0f),
            fmaxf(di * A.y + __ldg(&b1[fb+1]), 0.0f),
            fmaxf(di * A.z + __ldg(&b1[fb+2]), 0.0f),
            fmaxf(di * A.w + __ldg(&b1[fb+3]), 0.0f));
        float4 rb = make_float4(
            fmaxf(di * B.x + __ldg(&b1[fb+4]), 0.0f),
            fmaxf(di * B.y + __ldg(&b1[fb+5]), 0.0f),
            fmaxf(di * B.z + __ldg(&b1[fb+6]), 0.0f),
            fmaxf(di * B.w + __ldg(&b1[fb+7]), 0.0f));
        float4* hp = (float4*)&g_h[(size_t)warp * HH];
        hp[2*lane+0] = ra;
        hp[2*lane+1] = rb;
    }
}

// BN statistics over g_h
__global__ void k_stats(int n) {
    __shared__ float sred[2 * HH];
    int t = threadIdx.x;
    if (t < 2 * HH) sred[t] = 0.0f;
    __syncthreads();

    float ls[HH], lq[HH];
    #pragma unroll
    for (int j = 0; j < HH; j++) { ls[j] = 0.0f; lq[j] = 0.0f; }

    for (int node = blockIdx.x * blockDim.x + t; node < n;
         node += gridDim.x * blockDim.x) {
        const float4* hp = (const float4*)&g_h[(size_t)node * HH];
        #pragma unroll
        for (int q = 0; q < 4; q++) {
            float4 a = hp[q];
            ls[4*q+0] += a.x; lq[4*q+0] += a.x * a.x;
            ls[4*q+1] += a.y; lq[4*q+1] += a.y * a.y;
            ls[4*q+2] += a.z; lq[4*q+2] += a.z * a.z;
            ls[4*q+3] += a.w; lq[4*q+3] += a.w * a.w;
        }
    }
    #pragma unroll
    for (int j = 0; j < HH; j++) {
        #pragma unroll
        for (int off = 16; off; off >>= 1) {
            ls[j] += __shfl_xor_sync(0xffffffffu, ls[j], off);
            lq[j] += __shfl_xor_sync(0xffffffffu, lq[j], off);
        }
    }
    if ((t & 31) == 0) {
        #pragma unroll
        for (int j = 0; j < HH; j++) {
            atomicAdd(&sred[j], ls[j]);
            atomicAdd(&sred[HH + j], lq[j]);
        }
    }
    __syncthreads();
    if (t < 2 * HH) atomicAdd(&g_stats[t], sred[t]);
}

// BN finalize + apply + 10 residual hops + dinv pre-scale -> g_h2s (fp16)
__global__ void k_hops(const float* __restrict__ Wl, const float* __restrict__ bl,
                       const float* __restrict__ gamma, const float* __restrict__ beta,
                       float invN, int n) {
    __shared__ float swl[HH * HH];
    __shared__ float sbl[HH], ssc[HH], ssh[HH];
    int t = threadIdx.x;
    if (t < HH * HH) swl[t] = Wl[t];
    if (t < HH) {
        float mean = g_stats[t] * invN;
        float var  = g_stats[HH + t] * invN - mean * mean;
        float sc   = gamma[t] * rsqrtf(var + BN_EPS);
        ssc[t] = sc;
        ssh[t] = beta[t] - mean * sc;
        sbl[t] = bl[t];
    }
    __syncthreads();

    int node = blockIdx.x * blockDim.x + t;
    if (node >= n) return;

    float v[HH];
    const float4* hp = (const float4*)&g_h[(size_t)node * HH];
    #pragma unroll
    for (int q = 0; q < 4; q++) {
        float4 a = hp[q];
        v[4*q+0] = a.x; v[4*q+1] = a.y; v[4*q+2] = a.z; v[4*q+3] = a.w;
    }
    #pragma unroll
    for (int j = 0; j < HH; j++) v[j] = v[j] * ssc[j] + ssh[j];

    #pragma unroll 1
    for (int it = 0; it < 10; it++) {
        float acc[HH];
        #pragma unroll
        for (int j = 0; j < HH; j++) acc[j] = sbl[j];
        #pragma unroll
        for (int k = 0; k < HH; k++) {
            float hk = v[k];
            const float4* wr = (const float4*)&swl[k * HH];
            #pragma unroll
            for (int q = 0; q < 4; q++) {
                float4 w = wr[q];
                acc[4*q+0] += hk * w.x;
                acc[4*q+1] += hk * w.y;
                acc[4*q+2] += hk * w.z;
                acc[4*q+3] += hk * w.w;
            }
        }
        #pragma unroll
        for (int j = 0; j < HH; j++)
            v[j] = ALPHA * fmaxf(acc[j], 0.0f) + (1.0f - ALPHA) * v[j];
    }

    float di = g_dinv[node];
    uint2 pk[2];
    #pragma unroll
    for (int q = 0; q < 2; q++) {
        __half2 p0 = __floats2half2_rn(v[8*q+0]*di, v[8*q+1]*di);
        __half2 p1 = __floats2half2_rn(v[8*q+2]*di, v[8*q+3]*di);
        __half2 p2 = __floats2half2_rn(v[8*q+4]*di, v[8*q+5]*di);
        __half2 p3 = __floats2half2_rn(v[8*q+6]*di, v[8*q+7]*di);
        pk[0].x = *reinterpret_cast<unsigned*>(&p0);
        pk[0].y = *reinterpret_cast<unsigned*>(&p1);
        pk[1].x = *reinterpret_cast<unsigned*>(&p2);
        pk[1].y = *reinterpret_cast<unsigned*>(&p3);
        ((uint4*)&g_h2s[(size_t)node * HH])[q] =
            make_uint4(pk[0].x, pk[0].y, pk[1].x, pk[1].y);
    }
}

// conv2 aggregation (fp16 gather) fused with W2 GEMM + log_softmax.
__global__ void __launch_bounds__(256) k_agg2_final(const float* __restrict__ W2,
                                                    const float* __restrict__ b2,
                                                    float* __restrict__ out, int n) {
    __shared__ float sw2[HH * CC];
    __shared__ float sb2[CC];
    int t = threadIdx.x;
    for (int i = t; i < HH * CC; i += 256) sw2[i] = W2[i];
    if (t < CC) sb2[t] = b2[t];
    __syncthreads();

    int warp = (blockIdx.x * blockDim.x + t) >> 5;
    if (warp >= n) return;

    int lane = t & 31;
    int slot = lane >> 1;
    int c    = lane & 1;
    int beg = g_off[warp] + g_bpre[warp >> 9];
    int cnt = g_cnt[warp];

    const uint4* inp = (const uint4*)g_h2s;
    float4 A = make_float4(0.f, 0.f, 0.f, 0.f);
    float4 B = make_float4(0.f, 0.f, 0.f, 0.f);
    if (slot == 0) acc_h16(A, B, inp[(size_t)warp * 2 + c]);   // self loop
    gather_row_sum16(inp, beg, cnt, slot, c, A, B);

    #pragma unroll
    for (int off = 2; off < 32; off <<= 1) {
        A.x += __shfl_xor_sync(0xffffffffu, A.x, off);
        A.y += __shfl_xor_sync(0xffffffffu, A.y, off);
        A.z += __shfl_xor_sync(0xffffffffu, A.z, off);
        A.w += __shfl_xor_sync(0xffffffffu, A.w, off);
        B.x += __shfl_xor_sync(0xffffffffu, B.x, off);
        B.y += __shfl_xor_sync(0xffffffffu, B.y, off);
        B.z += __shfl_xor_sync(0xffffffffu, B.z, off);
        B.w += __shfl_xor_sync(0xffffffffu, B.w, off);
    }

    float di = g_dinv[warp];
    A.x *= di; A.y *= di; A.z *= di; A.w *= di;
    B.x *= di; B.y *= di; B.z *= di; B.w *= di;

    // lane0 holds features 0-7 (A=0-3, B=4-7); lane1 holds 8-15
    float v[HH];
    v[0]  = __shfl_sync(0xffffffffu, A.x, 0);
    v[1]  = __shfl_sync(0xffffffffu, A.y, 0);
    v[2]  = __shfl_sync(0xffffffffu, A.z, 0);
    v[3]  = __shfl_sync(0xffffffffu, A.w, 0);
    v[4]  = __shfl_sync(0xffffffffu, B.x, 0);
    v[5]  = __shfl_sync(0xffffffffu, B.y, 0);
    v[6]  = __shfl_sync(0xffffffffu, B.z, 0);
    v[7]  = __shfl_sync(0xffffffffu, B.w, 0);
    v[8]  = __shfl_sync(0xffffffffu, A.x, 1);
    v[9]  = __shfl_sync(0xffffffffu, A.y, 1);
    v[10] = __shfl_sync(0xffffffffu, A.z, 1);
    v[11] = __shfl_sync(0xffffffffu, A.w, 1);
    v[12] = __shfl_sync(0xffffffffu, B.x, 1);
    v[13] = __shfl_sync(0xffffffffu, B.y, 1);
    v[14] = __shfl_sync(0xffffffffu, B.z, 1);
    v[15] = __shfl_sync(0xffffffffu, B.w, 1);

    float o0 = sb2[lane];
    float o1 = (lane < CC - 32) ? sb2[32 + lane] : -1e30f;
    #pragma unroll
    for (int k = 0; k < HH; k++) {
        o0 += v[k] * sw2[k * CC + lane];
        if (lane < CC - 32) o1 += v[k] * sw2[k * CC + 32 + lane];
    }

    float m = fmaxf(o0, o1);
    #pragma unroll
    for (int off = 16; off; off >>= 1)
        m = fmaxf(m, __shfl_xor_sync(0xffffffffu, m, off));
    float s = expf(o0 - m) + ((lane < CC - 32) ? expf(o1 - m) : 0.0f);
    #pragma unroll
    for (int off = 16; off; off >>= 1)
        s += __shfl_xor_sync(0xffffffffu, s, off);
    float lse = m + logf(s);

    float* orow = out + (size_t)warp * CC;
    orow[lane] = o0 - lse;
    if (lane < CC - 32) orow[32 + lane] = o1 - lse;
}

// ---------------- launch ----------------
extern "C" void kernel_launch(void* const* d_in, const int* in_sizes, int n_in,
                              void* d_out, int out_size) {
    const float* x     = (const float*)d_in[0];
    const int*   src   = (const int*)d_in[1];
    const int*   dst   = (const int*)d_in[2];
    const float* W1    = (const float*)d_in[3];
    const float* b1    = (const float*)d_in[4];
    const float* gamma = (const float*)d_in[5];
    const float* beta  = (const float*)d_in[6];
    const float* Wl    = (const float*)d_in[7];
    const float* bl    = (const float*)d_in[8];
    const float* W2    = (const float*)d_in[9];
    const float* b2    = (const float*)d_in[10];
    float* out = (float*)d_out;

    int n  = in_sizes[0] / FF;
    int ne = in_sizes[1];
    if (n > NN) n = NN;
    if (ne > EE) ne = EE;

    int nb256 = (n + 255) / 256;
    int nscan = (n + SB - 1) / SB;             // <= 196
    int eb4   = (ne / 4 + 255) / 256 + 1;      // 4 edges per thread
    int aggblocks = (n * 32 + 255) / 256;      // warp per node

    k_init<<<nb256, 256>>>(n);
    k_cnt<<<eb4, 256>>>(dst, ne);
    k_scan1<<<nscan, SB>>>(n);
    k_fill<<<eb4, 256>>>(src, dst, ne);
    k_mm1<<<(n + TILE - 1) / TILE, 256>>>(x, W1, n);
    k_agg1<<<aggblocks, 256>>>(b1, n);
    k_stats<<<256, 256>>>(n);
    k_hops<<<nb256, 256>>>(Wl, bl, gamma, beta, 1.0f / (float)n, n);
    k_agg2_final<<<aggblocks, 256>>>(W2, b2, out, n);
}

// round 8
// speedup vs baseline: 1.0775x; 1.0775x over previous
#include <cuda_runtime.h>
#include <cuda_fp16.h>
#include <math.h>

#define NN 100000
#define EE 3200000
#define FF 128
#define HH 16
#define CC 40
#define ALPHA 0.1f
#define BN_EPS 1e-5f
#define SB 512                 // scan block size

// ---------------- scratch (device globals; no allocation) ----------------
__device__ __align__(16) __half g_tmps[NN * HH];  // fp16 (x@W1)*dinv (src-side, conv1)
__device__ __align__(16) __half g_h2s[NN * HH];   // fp16 post-hops hidden * dinv (src-side)
__device__ __align__(16) float g_h[NN * HH];      // fp32 post-relu hidden
__device__ float g_dinv[NN];
__device__ float g_stats[2 * HH];
// CSR machinery
__device__ int g_cnt[NN];          // in-degree (no self loop)
__device__ int g_off[NN];          // CSR row start (block-LOCAL; add g_bpre[node/SB])
__device__ int g_btot[256];        // scan block totals
__device__ int g_bpre[256];        // scan block prefixes
__device__ int g_flag;             // last-block counter for scan1
__device__ int g_rank[EE];         // per-edge rank within its dst row
__device__ int g_csr[EE];          // src indices grouped by dst

// ---------------- helpers ----------------
__device__ __forceinline__ float4 h8_to_f4(uint2 a) {
    __half2 h0 = *reinterpret_cast<__half2*>(&a.x);
    __half2 h1 = *reinterpret_cast<__half2*>(&a.y);
    float2 f0 = __half22float2(h0);
    float2 f1 = __half22float2(h1);
    return make_float4(f0.x, f0.y, f1.x, f1.y);
}
__device__ __forceinline__ void acc4(float4& a, float4 v) {
    a.x += v.x; a.y += v.y; a.z += v.z; a.w += v.w;
}

// ---------------- setup kernels ----------------

__global__ void k_init(int n) {
    int i = blockIdx.x * blockDim.x + threadIdx.x;
    if (i < n) g_cnt[i] = 0;
    if (i < 2 * HH) g_stats[i] = 0.0f;
    if (i == 2 * HH) g_flag = 0;
}

// count in-degrees AND record each edge's rank within its dst row (4 edges/thread)
__global__ void k_cnt(const int* __restrict__ dst, int ne) {
    int i = blockIdx.x * blockDim.x + threadIdx.x;
    int base = i * 4;
    if (base + 3 < ne) {
        int4 d = ((const int4*)dst)[i];
        int r0 = atomicAdd(&g_cnt[d.x], 1);
        int r1 = atomicAdd(&g_cnt[d.y], 1);
        int r2 = atomicAdd(&g_cnt[d.z], 1);
        int r3 = atomicAdd(&g_cnt[d.w], 1);
        ((int4*)g_rank)[i] = make_int4(r0, r1, r2, r3);
    } else {
        for (int e = base; e < ne; e++) g_rank[e] = atomicAdd(&g_cnt[dst[e]], 1);
    }
}

// block-local exclusive scan of g_cnt + dinv init; last block scans totals.
__global__ void k_scan1(int n) {
    __shared__ int wsum[SB / 32];
    __shared__ int isLast;
    int t = threadIdx.x, b = blockIdx.x;
    int i = b * SB + t;
    int v = (i < n) ? g_cnt[i] : 0;
    int x = v;
    #pragma unroll
    for (int off = 1; off < 32; off <<= 1) {
        int y = __shfl_up_sync(0xffffffffu, x, off);
        if ((t & 31) >= off) x += y;
    }
    if ((t & 31) == 31) wsum[t >> 5] = x;
    __syncthreads();
    if (t < SB / 32) {
        int w = wsum[t];
        #pragma unroll
        for (int off = 1; off < SB / 32; off <<= 1) {
            int y = __shfl_up_sync((1u << (SB / 32)) - 1u, w, off);
            if (t >= off) w += y;
        }
        wsum[t] = w;
    }
    __syncthreads();
    int prefix = (t >= 32) ? wsum[(t >> 5) - 1] : 0;
    if (i < n) {
        g_off[i] = prefix + x - v;
        g_dinv[i] = rsqrtf((float)(v + 1));   // +1 self loop
    }
    if (t == SB - 1) g_btot[b] = prefix + x;

    __threadfence();
    __syncthreads();
    if (t == 0) {
        int c = atomicAdd(&g_flag, 1);
        isLast = (c == gridDim.x - 1);
    }
    __syncthreads();
    if (!isLast) return;

    int nb = gridDim.x;                  // <= 256
    if (t < 256) {
        __shared__ int wsum2[8];
        int bv = (t < nb) ? g_btot[t] : 0;
        int bx = bv;
        #pragma unroll
        for (int off = 1; off < 32; off <<= 1) {
            int y = __shfl_up_sync(0xffffffffu, bx, off);
            if ((t & 31) >= off) bx += y;
        }
        if ((t & 31) == 31) wsum2[t >> 5] = bx;
        __syncthreads();
        if (t < 8) {
            int w = wsum2[t];
            #pragma unroll
            for (int off = 1; off < 8; off <<= 1) {
                int y = __shfl_up_sync(0xffu, w, off);
                if (t >= off) w += y;
            }
            wsum2[t] = w;
        }
        __syncthreads();
        int bpre = (t >= 32) ? wsum2[(t >> 5) - 1] : 0;
        if (t < nb) g_bpre[t] = bpre + bx - bv;
    }
}

// ATOMIC-FREE fill: p = off[d] + bpre + rank[e]; csr[p] = src[e]. 4 edges/thread.
__global__ void k_fill(const int* __restrict__ src, const int* __restrict__ dst, int ne) {
    int i = blockIdx.x * blockDim.x + threadIdx.x;
    int base = i * 4;
    if (base + 3 < ne) {
        int4 d = ((const int4*)dst)[i];
        int4 s = ((const int4*)src)[i];
        int4 r = ((const int4*)g_rank)[i];
        int p0 = g_off[d.x] + g_bpre[d.x >> 9] + r.x;
        int p1 = g_off[d.y] + g_bpre[d.y >> 9] + r.y;
        int p2 = g_off[d.z] + g_bpre[d.z >> 9] + r.z;
        int p3 = g_off[d.w] + g_bpre[d.w >> 9] + r.w;
        g_csr[p0] = s.x;
        g_csr[p1] = s.y;
        g_csr[p2] = s.z;
        g_csr[p3] = s.w;
    } else {
        for (int e = base; e < ne; e++) {
            int d = dst[e];
            g_csr[g_off[d] + g_bpre[d >> 9] + g_rank[e]] = src[e];
        }
    }
}

// ---------------- compute kernels ----------------

// x[N,128] @ W1[128,16] * dinv -> g_tmps (fp16). 64-node smem tile, 4 threads/node.
#define TILE 64
__global__ void __launch_bounds__(256) k_mm1(const float* __restrict__ x,
                                             const float* __restrict__ W1, int n) {
    __shared__ float4 xs[TILE][33];
    __shared__ float w1s[FF * HH];
    int t = threadIdx.x;
    int base = blockIdx.x * TILE;

    #pragma unroll
    for (int i = t; i < FF * HH; i += 256) w1s[i] = W1[i];

    const float4* xg = (const float4*)x;
    #pragma unroll
    for (int i = t; i < TILE * 32; i += 256) {
        int r = i >> 5, c = i & 31;
        float4 v = make_float4(0.f, 0.f, 0.f, 0.f);
        if (base + r < n) v = xg[(size_t)(base + r) * 32 + c];
        xs[r][c] = v;
    }
    __syncthreads();

    int ni = t >> 2;
    int jg = t & 3;
    int node = base + ni;

    const float* xrow = (const float*)&xs[ni][0];
    float a0 = 0.f, a1 = 0.f, a2 = 0.f, a3 = 0.f;
    #pragma unroll 8
    for (int k = 0; k < FF; k++) {
        float xv = xrow[k];
        float4 w = *(const float4*)&w1s[k * HH + jg * 4];
        a0 += xv * w.x; a1 += xv * w.y; a2 += xv * w.z; a3 += xv * w.w;
    }

    if (node < n) {
        float di = g_dinv[node];
        __half2 p0 = __floats2half2_rn(a0 * di, a1 * di);
        __half2 p1 = __floats2half2_rn(a2 * di, a3 * di);
        uint2 pk;
        pk.x = *reinterpret_cast<unsigned*>(&p0);
        pk.y = *reinterpret_cast<unsigned*>(&p1);
        ((uint2*)&g_tmps[(size_t)node * HH])[jg] = pk;
    }
}

// gather body (R6 form): 8 slots, uint2 per lane, 4 idx + 4 gathers in flight
__device__ __forceinline__ float4 gather_row_sum(const uint2* __restrict__ inp,
                                                 int beg, int cnt, int slot, int c) {
    float4 acc = make_float4(0.f, 0.f, 0.f, 0.f);
    int j = slot;
    for (; j + 24 < cnt; j += 32) {
        int s0 = g_csr[beg + j];
        int s1 = g_csr[beg + j + 8];
        int s2 = g_csr[beg + j + 16];
        int s3 = g_csr[beg + j + 24];
        uint2 r0 = inp[(size_t)s0 * 4 + c];
        uint2 r1 = inp[(size_t)s1 * 4 + c];
        uint2 r2 = inp[(size_t)s2 * 4 + c];
        uint2 r3 = inp[(size_t)s3 * 4 + c];
        acc4(acc, h8_to_f4(r0)); acc4(acc, h8_to_f4(r1));
        acc4(acc, h8_to_f4(r2)); acc4(acc, h8_to_f4(r3));
    }
    if (j + 8 < cnt) {
        int s0 = g_csr[beg + j];
        int s1 = g_csr[beg + j + 8];
        uint2 r0 = inp[(size_t)s0 * 4 + c];
        uint2 r1 = inp[(size_t)s1 * 4 + c];
        acc4(acc, h8_to_f4(r0)); acc4(acc, h8_to_f4(r1));
        j += 16;
    }
    if (j < cnt) {
        int s = g_csr[beg + j];
        acc4(acc, h8_to_f4(inp[(size_t)s * 4 + c]));
    }
    return acc;
}

// conv1 aggregation (fp16 gather, fp32 accum) + relu + bias -> g_h (fp32).
__global__ void __launch_bounds__(256) k_agg1(const float* __restrict__ b1, int n) {
    int t = threadIdx.x;
    int warp = (blockIdx.x * blockDim.x + t) >> 5;
    if (warp >= n) return;

    int lane = t & 31;
    int slot = lane >> 2;
    int c    = lane & 3;
    int beg = g_off[warp] + g_bpre[warp >> 9];
    int cnt = g_cnt[warp];

    const uint2* inp = (const uint2*)g_tmps;
    float4 acc = gather_row_sum(inp, beg, cnt, slot, c);
    if (slot == 0) acc4(acc, h8_to_f4(inp[(size_t)warp * 4 + c]));  // self loop

    #pragma unroll
    for (int off = 4; off < 32; off <<= 1) {
        acc.x += __shfl_xor_sync(0xffffffffu, acc.x, off);
        acc.y += __shfl_xor_sync(0xffffffffu, acc.y, off);
        acc.z += __shfl_xor_sync(0xffffffffu, acc.z, off);
        acc.w += __shfl_xor_sync(0xffffffffu, acc.w, off);
    }
    if (lane < 4) {
        float di = g_dinv[warp];
        float h0 = fmaxf(di * acc.x + __ldg(&b1[4*lane+0]), 0.0f);
        float h1 = fmaxf(di * acc.y + __ldg(&b1[4*lane+1]), 0.0f);
        float h2 = fmaxf(di * acc.z + __ldg(&b1[4*lane+2]), 0.0f);
        float h3 = fmaxf(di * acc.w + __ldg(&b1[4*lane+3]), 0.0f);
        ((float4*)&g_h[(size_t)warp * HH])[lane] = make_float4(h0, h1, h2, h3);
    }
}

// BN statistics over g_h
__global__ void k_stats(int n) {
    __shared__ float sred[2 * HH];
    int t = threadIdx.x;
    if (t < 2 * HH) sred[t] = 0.0f;
    __syncthreads();

    float ls[HH], lq[HH];
    #pragma unroll
    for (int j = 0; j < HH; j++) { ls[j] = 0.0f; lq[j] = 0.0f; }

    for (int node = blockIdx.x * blockDim.x + t; node < n;
         node += gridDim.x * blockDim.x) {
        const float4* hp = (const float4*)&g_h[(size_t)node * HH];
        #pragma unroll
        for (int q = 0; q < 4; q++) {
            float4 a = hp[q];
            ls[4*q+0] += a.x; lq[4*q+0] += a.x * a.x;
            ls[4*q+1] += a.y; lq[4*q+1] += a.y * a.y;
            ls[4*q+2] += a.z; lq[4*q+2] += a.z * a.z;
            ls[4*q+3] += a.w; lq[4*q+3] += a.w * a.w;
        }
    }
    #pragma unroll
    for (int j = 0; j < HH; j++) {
        #pragma unroll
        for (int off = 16; off; off >>= 1) {
            ls[j] += __shfl_xor_sync(0xffffffffu, ls[j], off);
            lq[j] += __shfl_xor_sync(0xffffffffu, lq[j], off);
        }
    }
    if ((t & 31) == 0) {
        #pragma unroll
        for (int j = 0; j < HH; j++) {
            atomicAdd(&sred[j], ls[j]);
            atomicAdd(&sred[HH + j], lq[j]);
        }
    }
    __syncthreads();
    if (t < 2 * HH) atomicAdd(&g_stats[t], sred[t]);
}

// BN finalize + apply + 10 residual hops + dinv pre-scale -> g_h2s (fp16)
__global__ void k_hops(const float* __restrict__ Wl, const float* __restrict__ bl,
                       const float* __restrict__ gamma, const float* __restrict__ beta,
                       float invN, int n) {
    __shared__ float swl[HH * HH];
    __shared__ float sbl[HH], ssc[HH], ssh[HH];
    int t = threadIdx.x;
    if (t < HH * HH) swl[t] = Wl[t];
    if (t < HH) {
        float mean = g_stats[t] * invN;
        float var  = g_stats[HH + t] * invN - mean * mean;
        float sc   = gamma[t] * rsqrtf(var + BN_EPS);
        ssc[t] = sc;
        ssh[t] = beta[t] - mean * sc;
        sbl[t] = bl[t];
    }
    __syncthreads();

    int node = blockIdx.x * blockDim.x + t;
    if (node >= n) return;

    float v[HH];
    const float4* hp = (const float4*)&g_h[(size_t)node * HH];
    #pragma unroll
    for (int q = 0; q < 4; q++) {
        float4 a = hp[q];
        v[4*q+0] = a.x; v[4*q+1] = a.y; v[4*q+2] = a.z; v[4*q+3] = a.w;
    }
    #pragma unroll
    for (int j = 0; j < HH; j++) v[j] = v[j] * ssc[j] + ssh[j];

    #pragma unroll 1
    for (int it = 0; it < 10; it++) {
        float acc[HH];
        #pragma unroll
        for (int j = 0; j < HH; j++) acc[j] = sbl[j];
        #pragma unroll
        for (int k = 0; k < HH; k++) {
            float hk = v[k];
            const float4* wr = (const float4*)&swl[k * HH];
            #pragma unroll
            for (int q = 0; q < 4; q++) {
                float4 w = wr[q];
                acc[4*q+0] += hk * w.x;
                acc[4*q+1] += hk * w.y;
                acc[4*q+2] += hk * w.z;
                acc[4*q+3] += hk * w.w;
            }
        }
        #pragma unroll
        for (int j = 0; j < HH; j++)
            v[j] = ALPHA * fmaxf(acc[j], 0.0f) + (1.0f - ALPHA) * v[j];
    }

    float di = g_dinv[node];
    uint2 pk[2];
    #pragma unroll
    for (int q = 0; q < 2; q++) {
        __half2 p0 = __floats2half2_rn(v[8*q+0]*di, v[8*q+1]*di);
        __half2 p1 = __floats2half2_rn(v[8*q+2]*di, v[8*q+3]*di);
        __half2 p2 = __floats2half2_rn(v[8*q+4]*di, v[8*q+5]*di);
        __half2 p3 = __floats2half2_rn(v[8*q+6]*di, v[8*q+7]*di);
        pk[0].x = *reinterpret_cast<unsigned*>(&p0);
        pk[0].y = *reinterpret_cast<unsigned*>(&p1);
        pk[1].x = *reinterpret_cast<unsigned*>(&p2);
        pk[1].y = *reinterpret_cast<unsigned*>(&p3);
        ((uint4*)&g_h2s[(size_t)node * HH])[q] =
            make_uint4(pk[0].x, pk[0].y, pk[1].x, pk[1].y);
    }
}

// conv2 aggregation (fp16 gather) fused with W2 GEMM + log_softmax.
__global__ void __launch_bounds__(256) k_agg2_final(const float* __restrict__ W2,
                                                    const float* __restrict__ b2,
                                                    float* __restrict__ out, int n) {
    __shared__ float sw2[HH * CC];
    __shared__ float sb2[CC];
    int t = threadIdx.x;
    for (int i = t; i < HH * CC; i += 256) sw2[i] = W2[i];
    if (t < CC) sb2[t] = b2[t];
    __syncthreads();

    int warp = (blockIdx.x * blockDim.x + t) >> 5;
    if (warp >= n) return;

    int lane = t & 31;
    int slot = lane >> 2;
    int c    = lane & 3;
    int beg = g_off[warp] + g_bpre[warp >> 9];
    int cnt = g_cnt[warp];

    const uint2* inp = (const uint2*)g_h2s;
    float4 acc = gather_row_sum(inp, beg, cnt, slot, c);
    if (slot == 0) acc4(acc, h8_to_f4(inp[(size_t)warp * 4 + c]));  // self loop

    #pragma unroll
    for (int off = 4; off < 32; off <<= 1) {
        acc.x += __shfl_xor_sync(0xffffffffu, acc.x, off);
        acc.y += __shfl_xor_sync(0xffffffffu, acc.y, off);
        acc.z += __shfl_xor_sync(0xffffffffu, acc.z, off);
        acc.w += __shfl_xor_sync(0xffffffffu, acc.w, off);
    }

    float di = g_dinv[warp];
    acc.x *= di; acc.y *= di; acc.z *= di; acc.w *= di;

    float v[HH];
    #pragma unroll
    for (int g = 0; g < 4; g++) {
        v[4*g+0] = __shfl_sync(0xffffffffu, acc.x, g);
        v[4*g+1] = __shfl_sync(0xffffffffu, acc.y, g);
        v[4*g+2] = __shfl_sync(0xffffffffu, acc.z, g);
        v[4*g+3] = __shfl_sync(0xffffffffu, acc.w, g);
    }

    float o0 = sb2[lane];
    float o1 = (lane < CC - 32) ? sb2[32 + lane] : -1e30f;
    #pragma unroll
    for (int k = 0; k < HH; k++) {
        o0 += v[k] * sw2[k * CC + lane];
        if (lane < CC - 32) o1 += v[k] * sw2[k * CC + 32 + lane];
    }

    float m = fmaxf(o0, o1);
    #pragma unroll
    for (int off = 16; off; off >>= 1)
        m = fmaxf(m, __shfl_xor_sync(0xffffffffu, m, off));
    float s = expf(o0 - m) + ((lane < CC - 32) ? expf(o1 - m) : 0.0f);
    #pragma unroll
    for (int off = 16; off; off >>= 1)
        s += __shfl_xor_sync(0xffffffffu, s, off);
    float lse = m + logf(s);

    float* orow = out + (size_t)warp * CC;
    orow[lane] = o0 - lse;
    if (lane < CC - 32) orow[32 + lane] = o1 - lse;
}

// ---------------- launch ----------------
extern "C" void kernel_launch(void* const* d_in, const int* in_sizes, int n_in,
                              void* d_out, int out_size) {
    const float* x     = (const float*)d_in[0];
    const int*   src   = (const int*)d_in[1];
    const int*   dst   = (const int*)d_in[2];
    const float* W1    = (const float*)d_in[3];
    const float* b1    = (const float*)d_in[4];
    const float* gamma = (const float*)d_in[5];
    const float* beta  = (const float*)d_in[6];
    const float* Wl    = (const float*)d_in[7];
    const float* bl    = (const float*)d_in[8];
    const float* W2    = (const float*)d_in[9];
    const float* b2    = (const float*)d_in[10];
    float* out = (float*)d_out;

    int n  = in_sizes[0] / FF;
    int ne = in_sizes[1];
    if (n > NN) n = NN;
    if (ne > EE) ne = EE;

    int nb256 = (n + 255) / 256;
    int nscan = (n + SB - 1) / SB;             // <= 196
    int eb4   = (ne / 4 + 255) / 256 + 1;      // 4 edges per thread
    int aggblocks = (n * 32 + 255) / 256;      // warp per node

    k_init<<<nb256, 256>>>(n);
    k_cnt<<<eb4, 256>>>(dst, ne);
    k_scan1<<<nscan, SB>>>(n);
    k_fill<<<eb4, 256>>>(src, dst, ne);
    k_mm1<<<(n + TILE - 1) / TILE, 256>>>(x, W1, n);
    k_agg1<<<aggblocks, 256>>>(b1, n);
    k_stats<<<256, 256>>>(n);
    k_hops<<<nb256, 256>>>(Wl, bl, gamma, beta, 1.0f / (float)n, n);
    k_agg2_final<<<aggblocks, 256>>>(W2, b2, out, n);
}